// round 12
// baseline (speedup 1.0000x reference)
#include <cuda_runtime.h>
#include <cuda_fp16.h>
#include <cstdint>

#define C_TOT 256
#define H_TOT 56
#define W_TOT 56
#define HW    3136
#define M_TOT 100352   // 32*56*56
#define CI    1024

// ---------------- scratch (static device globals; no allocations) ----------
__device__ __half g_y[(size_t)M_TOT * C_TOT];   // NHWC, BN'd, fp16
__device__ __half g_w1[CI * C_TOT];             // fc1_w fp16
__device__ __half g_w2[C_TOT * CI];             // fc2_w fp16

__device__ __forceinline__ float gelu_exact(float v) {
    return 0.5f * v * (1.0f + erff(v * 0.70710678118654752440f));
}

// ---------------- kernel 1: round weights to fp16 --------------------------
__global__ void convert_weights_kernel(const float* __restrict__ fc1,
                                       const float* __restrict__ fc2) {
    int i = blockIdx.x * blockDim.x + threadIdx.x;
    if (i < CI * C_TOT) {
        g_w1[i] = __float2half_rn(fc1[i]);
        g_w2[i] = __float2half_rn(fc2[i]);
    }
}

// ---------------- kernel 2: NeoCell + BN -> y (NHWC fp16, coalesced) --------
__global__ __launch_bounds__(256)
void neocell_bn_kernel(const float* __restrict__ x,
                       const float* __restrict__ wa1, const float* __restrict__ wb1,
                       const float* __restrict__ wa2, const float* __restrict__ wb2,
                       const float* __restrict__ bnw, const float* __restrict__ bnb,
                       const float* __restrict__ bnm, const float* __restrict__ bnv) {
    __shared__ float xs[32][257];
    const int bh = blockIdx.x;
    const int bw = blockIdx.y;
    const int b  = blockIdx.z;
    const int h0 = bh * 4, w0 = bw * 8;
    const int tid = threadIdx.x;

    const float* xb = x + (size_t)b * C_TOT * HW;
    #pragma unroll 4
    for (int p = 0; p < 32; p++) {
        int idx = tid + p * 256;
        int c = idx >> 5, r = idx & 31;
        int h = r >> 3, w = r & 7;
        xs[r][c] = xb[(size_t)c * HW + (h0 + h) * W_TOT + w0 + w];
    }
    __syncthreads();

    const int c = tid;
    const float scale = bnw[c] * rsqrtf(bnv[c] + 1e-5f);
    const float shift = bnb[c] - bnm[c] * scale;
    __half2 yv[16];

    if (c < 128) {
        const float a00 = wa1[c*4+0], a01 = wa1[c*4+1], a10 = wa1[c*4+2], a11 = wa1[c*4+3];
        const float b00 = wb1[c*4+0], b01 = wb1[c*4+1], b10 = wb1[c*4+2], b11 = wb1[c*4+3];
        #pragma unroll
        for (int n = 0; n < 2; n++)
            #pragma unroll
            for (int m = 0; m < 4; m++) {
                int r0 = (2*n) * 8 + 2*m;
                float x00 = xs[r0][c],     x01 = xs[r0 + 1][c];
                float x10 = xs[r0 + 8][c], x11 = xs[r0 + 9][c];
                float t00 = a00*x00 + a01*x10, t01 = a00*x01 + a01*x11;
                float t10 = a10*x00 + a11*x10, t11 = a10*x01 + a11*x11;
                float y00 = t00*b00 + t01*b10, y01 = t00*b01 + t01*b11;
                float y10 = t10*b00 + t11*b10, y11 = t10*b01 + t11*b11;
                yv[r0 >> 1]       = __floats2half2_rn(y00*scale+shift, y01*scale+shift);
                yv[(r0 + 8) >> 1] = __floats2half2_rn(y10*scale+shift, y11*scale+shift);
            }
    } else {
        const float* wap = wa2 + (size_t)(c - 128) * 16;
        const float* wbp = wb2 + (size_t)(c - 128) * 16;
        float a[4][4], bwt[4][4];
        #pragma unroll
        for (int i = 0; i < 4; i++)
            #pragma unroll
            for (int j = 0; j < 4; j++) { a[i][j] = wap[i*4+j]; bwt[i][j] = wbp[i*4+j]; }
        #pragma unroll
        for (int v = 0; v < 2; v++) {
            float xv[4][4];
            #pragma unroll
            for (int i = 0; i < 4; i++)
                #pragma unroll
                for (int j = 0; j < 4; j++) xv[i][j] = xs[i*8 + 4*v + j][c];
            float tv[4][4];
            #pragma unroll
            for (int p = 0; p < 4; p++)
                #pragma unroll
                for (int j = 0; j < 4; j++)
                    tv[p][j] = a[p][0]*xv[0][j] + a[p][1]*xv[1][j]
                             + a[p][2]*xv[2][j] + a[p][3]*xv[3][j];
            #pragma unroll
            for (int p = 0; p < 4; p++) {
                float y0 = tv[p][0]*bwt[0][0] + tv[p][1]*bwt[1][0] + tv[p][2]*bwt[2][0] + tv[p][3]*bwt[3][0];
                float y1 = tv[p][0]*bwt[0][1] + tv[p][1]*bwt[1][1] + tv[p][2]*bwt[2][1] + tv[p][3]*bwt[3][1];
                float y2 = tv[p][0]*bwt[0][2] + tv[p][1]*bwt[1][2] + tv[p][2]*bwt[2][2] + tv[p][3]*bwt[3][2];
                float y3 = tv[p][0]*bwt[0][3] + tv[p][1]*bwt[1][3] + tv[p][2]*bwt[2][3] + tv[p][3]*bwt[3][3];
                int r0 = p*8 + 4*v;
                yv[r0 >> 1]       = __floats2half2_rn(y0*scale+shift, y1*scale+shift);
                yv[(r0 + 2) >> 1] = __floats2half2_rn(y2*scale+shift, y3*scale+shift);
            }
        }
    }
    __syncthreads();

    __half* ys = (__half*)&xs[0][0];
    #pragma unroll
    for (int q = 0; q < 16; q++) {
        ys[(2*q)     * 256 + c] = __low2half(yv[q]);
        ys[(2*q + 1) * 256 + c] = __high2half(yv[q]);
    }
    __syncthreads();

    __half* yg = g_y + ((size_t)b * HW) * C_TOT;
    #pragma unroll
    for (int k = 0; k < 4; k++) {
        int idx = tid + k * 256;
        int p = idx >> 5, ch = idx & 31;
        int h = p >> 3, w = p & 7;
        uint4 v = ((const uint4*)ys)[p * 32 + ch];
        *(uint4*)&yg[((size_t)(h0 + h) * W_TOT + w0 + w) * C_TOT + ch * 8] = v;
    }
}

// ---------------- fused MLP kernel ------------------------------------------
// CTA = 64 M-rows, 256 threads (8 warps). smem layout (bytes):
//   [0, 32K)      A  : y block, 8 k-chunks x (64 rows x 64B), XOR-swizzled
//   [32K, 160K)   H  : h block, 32 k-chunks x (64 rows x 64B), XOR-swizzled
//   [160K, 224K)  STG: weight staging ring (phase1: 4 x 8KB; phase2: 4 x 16KB)
// Phase 1 (nb=0..7): h[:,128nb:128nb+128] = gelu(y @ w1_nbᵀ)  -> H (fp16)
// Phase 2: out = h @ w2ᵀ + x  (NCHW residual stores)
#define SM_A    0
#define SM_H    32768
#define SM_STG  163840
#define GSMEM   229376

#define LDSM(dst, addr)                                                                  \
    asm volatile("ldmatrix.sync.aligned.m8n8.x4.shared.b16 {%0,%1,%2,%3}, [%4];\n"       \
        : "=r"((dst)[0]), "=r"((dst)[1]), "=r"((dst)[2]), "=r"((dst)[3]) : "r"(addr))

#define MMA16(accj, afr, b0, b1)                                                         \
    asm volatile("mma.sync.aligned.m16n8k16.row.col.f32.f16.f16.f32 "                    \
        "{%0,%1,%2,%3}, {%4,%5,%6,%7}, {%8,%9}, {%0,%1,%2,%3};\n"                        \
        : "+f"((accj)[0]), "+f"((accj)[1]), "+f"((accj)[2]), "+f"((accj)[3])             \
        : "r"((afr)[0]), "r"((afr)[1]), "r"((afr)[2]), "r"((afr)[3]),                    \
          "r"(b0), "r"(b1))

#define CPA16(dst, src)                                                                  \
    asm volatile("cp.async.cg.shared.global [%0], [%1], 16;\n" :: "r"(dst), "l"(src))

__global__ __launch_bounds__(256, 1)
void fused_mlp_kernel(float* __restrict__ outp, const float* __restrict__ xres) {
    extern __shared__ __align__(16) __half sm[];
    const int tid  = threadIdx.x;
    const int lane = tid & 31;
    const int warp = tid >> 5;
    const int bm   = blockIdx.x * 64;
    const uint32_t smb = (uint32_t)__cvta_generic_to_shared(sm);

    const int lrow = tid >> 2;          // 0..63
    const int lck  = tid & 3;
    const int swc  = lck ^ ((lrow >> 1) & 3);

    // ldmatrix lane addressing (as R9)
    const int xrow = lane & 15;
    const int hi   = lane >> 4;
    const int csw  = (xrow >> 1) & 3;
    const uint32_t xb0 = (uint32_t)(((hi)     ^ csw) * 16);
    const uint32_t xb1 = (uint32_t)(((2 + hi) ^ csw) * 16);

    // ---- load A (y block 64x256) into smem, group #0 ----
    {
        const __half* Ag = g_y + (size_t)bm * C_TOT;
        #pragma unroll
        for (int p = 0; p < 8; p++) {
            int idx = tid + p * 256;
            int r = idx >> 5, j = idx & 31;           // j: 16B unit in 512B row
            int kc = j >> 2, cu = j & 3;
            uint32_t dst = smb + SM_A + (uint32_t)(kc * 4096 + r * 64
                              + ((cu ^ ((r >> 1) & 3)) * 16));
            CPA16(dst, Ag + (size_t)r * C_TOT + j * 8);
        }
        asm volatile("cp.async.commit_group;\n");
    }

#define PREFETCH1(gktv, stv) do {                                                        \
    int nb_ = (gktv) >> 3, kt_ = (gktv) & 7;                                             \
    uint32_t so_ = smb + SM_STG + (uint32_t)((stv) * 8192 + lrow * 64 + swc * 16);       \
    const __half* bp_ = g_w1 + (size_t)(nb_ * 128 + lrow) * C_TOT + kt_ * 32 + lck * 8;  \
    CPA16(so_,                     bp_);                                                 \
    CPA16(so_ + (uint32_t)(64*64), bp_ + (size_t)64 * C_TOT);                            \
    asm volatile("cp.async.commit_group;\n");                                            \
} while (0)

    // ---- phase 1: warps 2m x 4n, warp tile 32x32 ----
    {
        const int wm = warp & 1;
        const int wn = warp >> 1;                    // 0..3
        const uint32_t a1b = smb + SM_A   + (uint32_t)((wm * 32 + xrow) * 64);
        const uint32_t b1b = smb + SM_STG + (uint32_t)((wn * 32 + xrow) * 64);

        float acc1[2][4][4];
        #pragma unroll
        for (int i = 0; i < 2; i++)
            #pragma unroll
            for (int j = 0; j < 4; j++)
                #pragma unroll
                for (int q = 0; q < 4; q++) acc1[i][j][q] = 0.f;

        PREFETCH1(0, 0);
        PREFETCH1(1, 1);
        PREFETCH1(2, 2);

        for (int gkt = 0; gkt < 64; ++gkt) {
            const int st = gkt & 3;
            if (gkt + 2 < 64)      asm volatile("cp.async.wait_group 2;\n");
            else if (gkt + 1 < 64) asm volatile("cp.async.wait_group 1;\n");
            else                   asm volatile("cp.async.wait_group 0;\n");
            __syncthreads();
            if (gkt + 3 < 64) PREFETCH1(gkt + 3, (gkt + 3) & 3);

            const uint32_t aoff = (uint32_t)((gkt & 7) * 4096);
            const uint32_t soff = (uint32_t)(st * 8192);
            #pragma unroll
            for (int s = 0; s < 2; s++) {
                const uint32_t xb = s ? xb1 : xb0;
                uint32_t af[2][4];
                LDSM(af[0], a1b + aoff + xb);
                LDSM(af[1], a1b + aoff + xb + (uint32_t)(16 * 64));
                uint32_t bf[2][4];
                LDSM(bf[0], b1b + soff + xb);
                LDSM(bf[1], b1b + soff + xb + (uint32_t)(16 * 64));
                #pragma unroll
                for (int p = 0; p < 2; p++)
                    #pragma unroll
                    for (int mt = 0; mt < 2; mt++) {
                        MMA16(acc1[mt][2*p],   af[mt], bf[p][0], bf[p][2]);
                        MMA16(acc1[mt][2*p+1], af[mt], bf[p][1], bf[p][3]);
                    }
            }

            if ((gkt & 7) == 7) {
                const int nb = gkt >> 3;
                #pragma unroll
                for (int mt = 0; mt < 2; mt++) {
                    const int r0 = wm * 32 + mt * 16 + (lane >> 2);
                    const int r1 = r0 + 8;
                    #pragma unroll
                    for (int j = 0; j < 4; j++) {
                        const int ncl = wn * 32 + j * 8 + (lane & 3) * 2;
                        const int kc  = nb * 4 + (ncl >> 5);
                        const int cc  = ncl & 31;
                        const uint32_t u0 = smb + SM_H + (uint32_t)(kc * 4096 + r0 * 64
                                          + (((cc >> 3) ^ ((r0 >> 1) & 3)) * 16) + (cc & 7) * 2);
                        const uint32_t u1 = smb + SM_H + (uint32_t)(kc * 4096 + r1 * 64
                                          + (((cc >> 3) ^ ((r1 >> 1) & 3)) * 16) + (cc & 7) * 2);
                        __half2 v0 = __floats2half2_rn(gelu_exact(acc1[mt][j][0]),
                                                       gelu_exact(acc1[mt][j][1]));
                        __half2 v1 = __floats2half2_rn(gelu_exact(acc1[mt][j][2]),
                                                       gelu_exact(acc1[mt][j][3]));
                        asm volatile("st.shared.u32 [%0], %1;\n"
                                     :: "r"(u0), "r"(*(uint32_t*)&v0) : "memory");
                        asm volatile("st.shared.u32 [%0], %1;\n"
                                     :: "r"(u1), "r"(*(uint32_t*)&v1) : "memory");
                        #pragma unroll
                        for (int q = 0; q < 4; q++) acc1[mt][j][q] = 0.f;
                    }
                }
            }
        }
    }
#undef PREFETCH1

    __syncthreads();   // hbuf complete; stage region free

#define PREFETCH2(ktv, stv) do {                                                         \
    uint32_t so_ = smb + SM_STG + (uint32_t)((stv) * 16384 + lrow * 64 + swc * 16);      \
    const __half* bp_ = g_w2 + (size_t)lrow * CI + (ktv) * 32 + lck * 8;                 \
    _Pragma("unroll")                                                                    \
    for (int rp_ = 0; rp_ < 4; rp_++)                                                    \
        CPA16(so_ + (uint32_t)(rp_ * 64 * 64), bp_ + (size_t)(rp_ * 64) * CI);           \
    asm volatile("cp.async.commit_group;\n");                                            \
} while (0)

    // ---- phase 2: warps 2m x 4n, warp tile 32x64, K=1024 from hbuf ----
    {
        const int wm = warp & 1;
        const int wn = warp >> 1;                    // 0..3
        const uint32_t a2b = smb + SM_H   + (uint32_t)((wm * 32 + xrow) * 64);
        const uint32_t b2b = smb + SM_STG + (uint32_t)((wn * 64 + xrow) * 64);

        float acc2[2][8][4];
        #pragma unroll
        for (int i = 0; i < 2; i++)
            #pragma unroll
            for (int j = 0; j < 8; j++)
                #pragma unroll
                for (int q = 0; q < 4; q++) acc2[i][j][q] = 0.f;

        PREFETCH2(0, 0);
        PREFETCH2(1, 1);
        PREFETCH2(2, 2);

        for (int kt = 0; kt < 32; ++kt) {
            const int st = kt & 3;
            if (kt + 2 < 32)      asm volatile("cp.async.wait_group 2;\n");
            else if (kt + 1 < 32) asm volatile("cp.async.wait_group 1;\n");
            else                  asm volatile("cp.async.wait_group 0;\n");
            __syncthreads();
            if (kt + 3 < 32) PREFETCH2(kt + 3, (kt + 3) & 3);

            const uint32_t aoff = (uint32_t)(kt * 4096);
            const uint32_t soff = (uint32_t)(st * 16384);
            #pragma unroll
            for (int s = 0; s < 2; s++) {
                const uint32_t xb = s ? xb1 : xb0;
                uint32_t af[2][4];
                LDSM(af[0], a2b + aoff + xb);
                LDSM(af[1], a2b + aoff + xb + (uint32_t)(16 * 64));
                uint32_t bf[4][4];
                #pragma unroll
                for (int p = 0; p < 4; p++)
                    LDSM(bf[p], b2b + soff + xb + (uint32_t)(p * 16 * 64));
                #pragma unroll
                for (int p = 0; p < 4; p++)
                    #pragma unroll
                    for (int mt = 0; mt < 2; mt++) {
                        MMA16(acc2[mt][2*p],   af[mt], bf[p][0], bf[p][2]);
                        MMA16(acc2[mt][2*p+1], af[mt], bf[p][1], bf[p][3]);
                    }
            }
        }

        // epilogue: residual + NCHW stores
        #pragma unroll
        for (int mt = 0; mt < 2; mt++) {
            const int r0 = bm + wm * 32 + mt * 16 + (lane >> 2);
            const int r1 = r0 + 8;
            const int b0 = r0 / HW, hw0 = r0 - b0 * HW;
            const int b1 = r1 / HW, hw1 = r1 - b1 * HW;
            const size_t base0 = (size_t)b0 * C_TOT * HW + hw0;
            const size_t base1 = (size_t)b1 * C_TOT * HW + hw1;
            #pragma unroll
            for (int j = 0; j < 8; j++) {
                const int nc = wn * 64 + j * 8 + (lane & 3) * 2;
                size_t i0 = base0 + (size_t)nc * HW;
                outp[i0]      = acc2[mt][j][0] + xres[i0];
                outp[i0 + HW] = acc2[mt][j][1] + xres[i0 + HW];
                size_t i1 = base1 + (size_t)nc * HW;
                outp[i1]      = acc2[mt][j][2] + xres[i1];
                outp[i1 + HW] = acc2[mt][j][3] + xres[i1 + HW];
            }
        }
    }
#undef PREFETCH2
}

// ---------------- launch ----------------------------------------------------
extern "C" void kernel_launch(void* const* d_in, const int* in_sizes, int n_in,
                              void* d_out, int out_size) {
    const float* x   = (const float*)d_in[0];
    const float* wa1 = (const float*)d_in[1];
    const float* wb1 = (const float*)d_in[2];
    const float* wa2 = (const float*)d_in[3];
    const float* wb2 = (const float*)d_in[4];
    const float* bnw = (const float*)d_in[5];
    const float* bnb = (const float*)d_in[6];
    const float* bnm = (const float*)d_in[7];
    const float* bnv = (const float*)d_in[8];
    const float* fc1 = (const float*)d_in[9];
    const float* fc2 = (const float*)d_in[10];
    float* out = (float*)d_out;

    cudaFuncSetAttribute(fused_mlp_kernel,
                         cudaFuncAttributeMaxDynamicSharedMemorySize, GSMEM);

    convert_weights_kernel<<<(CI * C_TOT + 255) / 256, 256>>>(fc1, fc2);
    neocell_bn_kernel<<<dim3(14, 7, 32), 256>>>(x, wa1, wb1, wa2, wb2,
                                                bnw, bnb, bnm, bnv);
    fused_mlp_kernel<<<M_TOT / 64, 256, GSMEM>>>(out, x);
}

// round 13
// speedup vs baseline: 1.1517x; 1.1517x over previous
#include <cuda_runtime.h>
#include <cuda_fp16.h>
#include <cstdint>

#define C_TOT 256
#define H_TOT 56
#define W_TOT 56
#define HW    3136
#define M_TOT 100352   // 32*56*56
#define CI    1024

// ---------------- scratch (static device globals; no allocations) ----------
__device__ __half g_y[(size_t)M_TOT * C_TOT];   // NHWC, BN'd, fp16
__device__ __half g_h[(size_t)M_TOT * CI];      // GELU output, fp16
__device__ __half g_w1[CI * C_TOT];             // fc1_w fp16
__device__ __half g_w2[C_TOT * CI];             // fc2_w fp16

__device__ __forceinline__ float gelu_exact(float v) {
    return 0.5f * v * (1.0f + erff(v * 0.70710678118654752440f));
}

// ---------------- kernel 1: round weights to fp16 --------------------------
__global__ void convert_weights_kernel(const float* __restrict__ fc1,
                                       const float* __restrict__ fc2) {
    int i = blockIdx.x * blockDim.x + threadIdx.x;
    if (i < CI * C_TOT) {
        g_w1[i] = __float2half_rn(fc1[i]);
        g_w2[i] = __float2half_rn(fc2[i]);
    }
}

// ---------------- kernel 2: NeoCell + BN -> y (NHWC fp16, coalesced) --------
__global__ __launch_bounds__(256)
void neocell_bn_kernel(const float* __restrict__ x,
                       const float* __restrict__ wa1, const float* __restrict__ wb1,
                       const float* __restrict__ wa2, const float* __restrict__ wb2,
                       const float* __restrict__ bnw, const float* __restrict__ bnb,
                       const float* __restrict__ bnm, const float* __restrict__ bnv) {
    __shared__ float xs[32][257];
    const int bh = blockIdx.x;
    const int bw = blockIdx.y;
    const int b  = blockIdx.z;
    const int h0 = bh * 4, w0 = bw * 8;
    const int tid = threadIdx.x;

    const float* xb = x + (size_t)b * C_TOT * HW;
    #pragma unroll 4
    for (int p = 0; p < 32; p++) {
        int idx = tid + p * 256;
        int c = idx >> 5, r = idx & 31;
        int h = r >> 3, w = r & 7;
        xs[r][c] = xb[(size_t)c * HW + (h0 + h) * W_TOT + w0 + w];
    }
    __syncthreads();

    const int c = tid;
    const float scale = bnw[c] * rsqrtf(bnv[c] + 1e-5f);
    const float shift = bnb[c] - bnm[c] * scale;
    __half2 yv[16];

    if (c < 128) {
        const float a00 = wa1[c*4+0], a01 = wa1[c*4+1], a10 = wa1[c*4+2], a11 = wa1[c*4+3];
        const float b00 = wb1[c*4+0], b01 = wb1[c*4+1], b10 = wb1[c*4+2], b11 = wb1[c*4+3];
        #pragma unroll
        for (int n = 0; n < 2; n++)
            #pragma unroll
            for (int m = 0; m < 4; m++) {
                int r0 = (2*n) * 8 + 2*m;
                float x00 = xs[r0][c],     x01 = xs[r0 + 1][c];
                float x10 = xs[r0 + 8][c], x11 = xs[r0 + 9][c];
                float t00 = a00*x00 + a01*x10, t01 = a00*x01 + a01*x11;
                float t10 = a10*x00 + a11*x10, t11 = a10*x01 + a11*x11;
                float y00 = t00*b00 + t01*b10, y01 = t00*b01 + t01*b11;
                float y10 = t10*b00 + t11*b10, y11 = t10*b01 + t11*b11;
                yv[r0 >> 1]       = __floats2half2_rn(y00*scale+shift, y01*scale+shift);
                yv[(r0 + 8) >> 1] = __floats2half2_rn(y10*scale+shift, y11*scale+shift);
            }
    } else {
        const float* wap = wa2 + (size_t)(c - 128) * 16;
        const float* wbp = wb2 + (size_t)(c - 128) * 16;
        float a[4][4], bwt[4][4];
        #pragma unroll
        for (int i = 0; i < 4; i++)
            #pragma unroll
            for (int j = 0; j < 4; j++) { a[i][j] = wap[i*4+j]; bwt[i][j] = wbp[i*4+j]; }
        #pragma unroll
        for (int v = 0; v < 2; v++) {
            float xv[4][4];
            #pragma unroll
            for (int i = 0; i < 4; i++)
                #pragma unroll
                for (int j = 0; j < 4; j++) xv[i][j] = xs[i*8 + 4*v + j][c];
            float tv[4][4];
            #pragma unroll
            for (int p = 0; p < 4; p++)
                #pragma unroll
                for (int j = 0; j < 4; j++)
                    tv[p][j] = a[p][0]*xv[0][j] + a[p][1]*xv[1][j]
                             + a[p][2]*xv[2][j] + a[p][3]*xv[3][j];
            #pragma unroll
            for (int p = 0; p < 4; p++) {
                float y0 = tv[p][0]*bwt[0][0] + tv[p][1]*bwt[1][0] + tv[p][2]*bwt[2][0] + tv[p][3]*bwt[3][0];
                float y1 = tv[p][0]*bwt[0][1] + tv[p][1]*bwt[1][1] + tv[p][2]*bwt[2][1] + tv[p][3]*bwt[3][1];
                float y2 = tv[p][0]*bwt[0][2] + tv[p][1]*bwt[1][2] + tv[p][2]*bwt[2][2] + tv[p][3]*bwt[3][2];
                float y3 = tv[p][0]*bwt[0][3] + tv[p][1]*bwt[1][3] + tv[p][2]*bwt[2][3] + tv[p][3]*bwt[3][3];
                int r0 = p*8 + 4*v;
                yv[r0 >> 1]       = __floats2half2_rn(y0*scale+shift, y1*scale+shift);
                yv[(r0 + 2) >> 1] = __floats2half2_rn(y2*scale+shift, y3*scale+shift);
            }
        }
    }
    __syncthreads();

    __half* ys = (__half*)&xs[0][0];
    #pragma unroll
    for (int q = 0; q < 16; q++) {
        ys[(2*q)     * 256 + c] = __low2half(yv[q]);
        ys[(2*q + 1) * 256 + c] = __high2half(yv[q]);
    }
    __syncthreads();

    __half* yg = g_y + ((size_t)b * HW) * C_TOT;
    #pragma unroll
    for (int k = 0; k < 4; k++) {
        int idx = tid + k * 256;
        int p = idx >> 5, ch = idx & 31;
        int h = p >> 3, w = p & 7;
        uint4 v = ((const uint4*)ys)[p * 32 + ch];
        *(uint4*)&yg[((size_t)(h0 + h) * W_TOT + w0 + w) * C_TOT + ch * 8] = v;
    }
}

// ---------------- shared GEMM building blocks -------------------------------
#define LDSM(dst, addr)                                                                  \
    asm volatile("ldmatrix.sync.aligned.m8n8.x4.shared.b16 {%0,%1,%2,%3}, [%4];\n"       \
        : "=r"((dst)[0]), "=r"((dst)[1]), "=r"((dst)[2]), "=r"((dst)[3]) : "r"(addr))

#define MMA16(accj, afr, b0, b1)                                                         \
    asm volatile("mma.sync.aligned.m16n8k16.row.col.f32.f16.f16.f32 "                    \
        "{%0,%1,%2,%3}, {%4,%5,%6,%7}, {%8,%9}, {%0,%1,%2,%3};\n"                        \
        : "+f"((accj)[0]), "+f"((accj)[1]), "+f"((accj)[2]), "+f"((accj)[3])             \
        : "r"((afr)[0]), "r"((afr)[1]), "r"((afr)[2]), "r"((afr)[3]),                    \
          "r"(b0), "r"(b1))

#define CPA16(dst, src)                                                                  \
    asm volatile("cp.async.cg.shared.global [%0], [%1], 16;\n" :: "r"(dst), "l"(src))

// ---------------- GEMM1 persistent: h = gelu(y @ w1^T) ----------------------
// grid (8, 98): CTA owns N-block bn (128 of 1024) and 8 M-tiles (128 rows each).
// smem: [0,64K) resident B (w1 slice, 8 k-chunks x 128row x 64B swizzled),
//       [64K,96K) A ring: 4 stages x 8KB. 128 threads, warps 2m x 2n, 64x64.
#define SM1_B   0
#define SM1_A   65536
#define GSMEM1  98304

__global__ __launch_bounds__(128, 2)
void gemm1_kernel() {
    extern __shared__ __align__(16) __half sm[];
    const int tid  = threadIdx.x;
    const int lane = tid & 31;
    const int warp = tid >> 5;
    const int wm   = warp & 1;
    const int wn   = warp >> 1;
    const int bn   = blockIdx.x * 128;
    const int mt0  = blockIdx.y * 8;          // first M-tile index
    const uint32_t smb = (uint32_t)__cvta_generic_to_shared(sm);

    const int lrow = tid >> 2;                // 0..31
    const int lck  = tid & 3;
    const int swc  = lck ^ ((lrow >> 1) & 3);

    const int xrow = lane & 15;
    const int hi   = lane >> 4;
    const int csw  = (xrow >> 1) & 3;
    const uint32_t xb0 = (uint32_t)(((hi)     ^ csw) * 16);
    const uint32_t xb1 = (uint32_t)(((2 + hi) ^ csw) * 16);

    // resident B load: 128 rows x 32 units (16B), swizzled into 8 k-chunks
    {
        const __half* Bg = g_w1 + (size_t)bn * C_TOT;
        #pragma unroll
        for (int p = 0; p < 32; p++) {
            int idx = tid + p * 128;
            int r = idx >> 5, j = idx & 31;
            int kc = j >> 2, cu = j & 3;
            uint32_t dst = smb + SM1_B + (uint32_t)(kc * 8192 + r * 64
                             + ((cu ^ ((r >> 1) & 3)) * 16));
            CPA16(dst, Bg + (size_t)r * C_TOT + j * 8);
        }
    }

#define PREF_A1(gkv, stv) do {                                                           \
    int bm_ = (mt0 + ((gkv) >> 3)) * 128, kt_ = (gkv) & 7;                               \
    uint32_t so_ = smb + SM1_A + (uint32_t)((stv) * 8192 + lrow * 64 + swc * 16);        \
    const __half* ap_ = g_y + (size_t)(bm_ + lrow) * C_TOT + kt_ * 32 + lck * 8;         \
    _Pragma("unroll")                                                                    \
    for (int rp_ = 0; rp_ < 4; rp_++)                                                    \
        CPA16(so_ + (uint32_t)(rp_ * 32 * 64), ap_ + (size_t)(rp_ * 32) * C_TOT);        \
    asm volatile("cp.async.commit_group;\n");                                            \
} while (0)

    PREF_A1(0, 0);   // commit closes B + A0 as group 0
    PREF_A1(1, 1);
    PREF_A1(2, 2);

    float acc[4][8][4];
    #pragma unroll
    for (int i = 0; i < 4; i++)
        #pragma unroll
        for (int j = 0; j < 8; j++)
            #pragma unroll
            for (int q = 0; q < 4; q++) acc[i][j][q] = 0.f;

    for (int gk = 0; gk < 64; ++gk) {
        const int st = gk & 3;
        if (gk + 2 < 64)      asm volatile("cp.async.wait_group 2;\n");
        else if (gk + 1 < 64) asm volatile("cp.async.wait_group 1;\n");
        else                  asm volatile("cp.async.wait_group 0;\n");
        __syncthreads();
        if (gk + 3 < 64) PREF_A1(gk + 3, (gk + 3) & 3);

        const uint32_t aoff = (uint32_t)(SM1_A + st * 8192);
        const uint32_t boff = (uint32_t)(SM1_B + (gk & 7) * 8192);
        #pragma unroll
        for (int s = 0; s < 2; s++) {
            const uint32_t xb = s ? xb1 : xb0;
            uint32_t af[4][4];
            #pragma unroll
            for (int mt = 0; mt < 4; mt++)
                LDSM(af[mt], smb + aoff + xb + (uint32_t)((wm * 64 + mt * 16 + xrow) * 64));
            uint32_t bf[4][4];
            #pragma unroll
            for (int p = 0; p < 4; p++)
                LDSM(bf[p], smb + boff + xb + (uint32_t)((wn * 64 + p * 16 + xrow) * 64));
            #pragma unroll
            for (int p = 0; p < 4; p++)
                #pragma unroll
                for (int mt = 0; mt < 4; mt++) {
                    MMA16(acc[mt][2*p],   af[mt], bf[p][0], bf[p][2]);
                    MMA16(acc[mt][2*p+1], af[mt], bf[p][1], bf[p][3]);
                }
        }

        if ((gk & 7) == 7) {
            const int bm = (mt0 + (gk >> 3)) * 128;
            #pragma unroll
            for (int mt = 0; mt < 4; mt++) {
                const int r0 = bm + wm * 64 + mt * 16 + (lane >> 2);
                #pragma unroll
                for (int j = 0; j < 8; j++) {
                    const int nc = bn + wn * 64 + j * 8 + (lane & 3) * 2;
                    __half2* p0 = (__half2*)(g_h + (size_t)r0 * CI + nc);
                    __half2* p1 = (__half2*)(g_h + (size_t)(r0 + 8) * CI + nc);
                    *p0 = __floats2half2_rn(gelu_exact(acc[mt][j][0]), gelu_exact(acc[mt][j][1]));
                    *p1 = __floats2half2_rn(gelu_exact(acc[mt][j][2]), gelu_exact(acc[mt][j][3]));
                    #pragma unroll
                    for (int q = 0; q < 4; q++) acc[mt][j][q] = 0.f;
                }
            }
        }
    }
#undef PREF_A1
}

// ---------------- GEMM2: out = h @ w2^T + x (NCHW residual) -----------------
// Exactly the R11 MODE 2 kernel. CTA 128x128, K=1024, 4 warps 64x64.
#define ROWB    64
#define A_STG   (128 * ROWB)
#define STG_B   (2 * A_STG)
#define GSMEM2  (4 * STG_B)     // 65536

__global__ __launch_bounds__(128, 2)
void gemm2_kernel(float* __restrict__ outp, const float* __restrict__ xres) {
    extern __shared__ __align__(16) __half sm[];
    constexpr int K = CI;
    constexpr int KT = K / 32;

    const int tid  = threadIdx.x;
    const int lane = tid & 31;
    const int warp = tid >> 5;
    const int wm   = warp & 1;
    const int wn   = warp >> 1;
    const int bm   = blockIdx.y * 128;
    const int bn   = blockIdx.x * 128;

    const int lrow = tid >> 2;
    const int lck  = tid & 3;
    const int swc  = lck ^ ((lrow >> 1) & 3);
    const __half* Ap = g_h  + (size_t)(bm + lrow) * K + lck * 8;
    const __half* Bp = g_w2 + (size_t)(bn + lrow) * K + lck * 8;

    const uint32_t smb = (uint32_t)__cvta_generic_to_shared(sm);
    const uint32_t sa  = smb + (uint32_t)(lrow * ROWB + swc * 16);
    const uint32_t sb  = sa + (uint32_t)A_STG;

    float acc[4][8][4];
    #pragma unroll
    for (int i = 0; i < 4; i++)
        #pragma unroll
        for (int j = 0; j < 8; j++)
            #pragma unroll
            for (int q = 0; q < 4; q++) acc[i][j][q] = 0.f;

    const int xrow = lane & 15;
    const int hi   = lane >> 4;
    const int csw  = (xrow >> 1) & 3;
    const uint32_t xb0 = (uint32_t)(((hi)     ^ csw) * 16);
    const uint32_t xb1 = (uint32_t)(((2 + hi) ^ csw) * 16);
    const uint32_t abase = smb + (uint32_t)((wm * 64 + xrow) * ROWB);
    const uint32_t bbase = smb + (uint32_t)(A_STG + (wn * 64 + xrow) * ROWB);

#define PREFETCH(ktv, stv) do {                                                          \
    const __half* ap_ = Ap + (ktv) * 32;                                                 \
    const __half* bp_ = Bp + (ktv) * 32;                                                 \
    uint32_t so_ = (uint32_t)((stv) * STG_B);                                            \
    _Pragma("unroll")                                                                    \
    for (int rp_ = 0; rp_ < 4; rp_++) {                                                  \
        asm volatile("cp.async.cg.shared.global [%0], [%1], 16;\n"                       \
                     :: "r"(sa + so_ + (uint32_t)(rp_ * 32 * ROWB)),                     \
                        "l"(ap_ + (size_t)(rp_ * 32) * K));                              \
        asm volatile("cp.async.cg.shared.global [%0], [%1], 16;\n"                       \
                     :: "r"(sb + so_ + (uint32_t)(rp_ * 32 * ROWB)),                     \
                        "l"(bp_ + (size_t)(rp_ * 32) * K));                              \
    }                                                                                    \
    asm volatile("cp.async.commit_group;\n");                                            \
} while (0)

    PREFETCH(0, 0);
    PREFETCH(1, 1);
    PREFETCH(2, 2);

    for (int kt = 0; kt < KT; ++kt) {
        const int st = kt & 3;
        if (kt + 2 < KT)      asm volatile("cp.async.wait_group 2;\n");
        else if (kt + 1 < KT) asm volatile("cp.async.wait_group 1;\n");
        else                  asm volatile("cp.async.wait_group 0;\n");
        __syncthreads();
        if (kt + 3 < KT) PREFETCH(kt + 3, (kt + 3) & 3);

        const uint32_t soff = (uint32_t)(st * STG_B);
        #pragma unroll
        for (int s = 0; s < 2; s++) {
            const uint32_t xb = soff + (s ? xb1 : xb0);
            uint32_t af[4][4];
            #pragma unroll
            for (int mt = 0; mt < 4; mt++)
                LDSM(af[mt], abase + xb + (uint32_t)(mt * 16 * ROWB));
            uint32_t bf[4][4];
            #pragma unroll
            for (int p = 0; p < 4; p++)
                LDSM(bf[p], bbase + xb + (uint32_t)(p * 16 * ROWB));
            #pragma unroll
            for (int p = 0; p < 4; p++)
                #pragma unroll
                for (int mt = 0; mt < 4; mt++) {
                    MMA16(acc[mt][2*p],   af[mt], bf[p][0], bf[p][2]);
                    MMA16(acc[mt][2*p+1], af[mt], bf[p][1], bf[p][3]);
                }
        }
    }
#undef PREFETCH

    #pragma unroll
    for (int mt = 0; mt < 4; mt++) {
        const int r0 = bm + wm * 64 + mt * 16 + (lane >> 2);
        const int r1 = r0 + 8;
        const int b0 = r0 / HW, hw0 = r0 - b0 * HW;
        const int b1 = r1 / HW, hw1 = r1 - b1 * HW;
        const size_t base0 = (size_t)b0 * C_TOT * HW + hw0;
        const size_t base1 = (size_t)b1 * C_TOT * HW + hw1;
        #pragma unroll
        for (int j = 0; j < 8; j++) {
            const int nc = bn + wn * 64 + j * 8 + (lane & 3) * 2;
            size_t i0 = base0 + (size_t)nc * HW;
            outp[i0]      = acc[mt][j][0] + xres[i0];
            outp[i0 + HW] = acc[mt][j][1] + xres[i0 + HW];
            size_t i1 = base1 + (size_t)nc * HW;
            outp[i1]      = acc[mt][j][2] + xres[i1];
            outp[i1 + HW] = acc[mt][j][3] + xres[i1 + HW];
        }
    }
}

// ---------------- launch ----------------------------------------------------
extern "C" void kernel_launch(void* const* d_in, const int* in_sizes, int n_in,
                              void* d_out, int out_size) {
    const float* x   = (const float*)d_in[0];
    const float* wa1 = (const float*)d_in[1];
    const float* wb1 = (const float*)d_in[2];
    const float* wa2 = (const float*)d_in[3];
    const float* wb2 = (const float*)d_in[4];
    const float* bnw = (const float*)d_in[5];
    const float* bnb = (const float*)d_in[6];
    const float* bnm = (const float*)d_in[7];
    const float* bnv = (const float*)d_in[8];
    const float* fc1 = (const float*)d_in[9];
    const float* fc2 = (const float*)d_in[10];
    float* out = (float*)d_out;

    cudaFuncSetAttribute(gemm1_kernel,
                         cudaFuncAttributeMaxDynamicSharedMemorySize, GSMEM1);
    cudaFuncSetAttribute(gemm2_kernel,
                         cudaFuncAttributeMaxDynamicSharedMemorySize, GSMEM2);

    convert_weights_kernel<<<(CI * C_TOT + 255) / 256, 256>>>(fc1, fc2);
    neocell_bn_kernel<<<dim3(14, 7, 32), 256>>>(x, wa1, wb1, wa2, wb2,
                                                bnw, bnb, bnm, bnv);
    gemm1_kernel<<<dim3(8, 98), 128, GSMEM1>>>();
    gemm2_kernel<<<dim3(2, 784), 128, GSMEM2>>>(out, x);
}